// round 14
// baseline (speedup 1.0000x reference)
#include <cuda_runtime.h>
#include <cuda_bf16.h>
#include <cuda_fp16.h>
#include <math.h>
#include <stdint.h>

#define N_NODES 50000
#define N_PAD   50048          // multiple of 128 for GEMM tiles
#define E_EDGES 800000
#define D       256
#define L       4
#define NB_SCAN 196            // ceil(N_NODES/256)

// ---------------- scratch (device globals; .bss zero-init, pads stay 0) ----
__device__ float g_h  [(size_t)N_PAD * D];
__device__ float g_zw [(size_t)N_PAD * D];
__device__ __half g_zwh[(size_t)N_PAD * D];   // fp16 mirror for neighbor gather
__device__ float g_deg [N_NODES];
__device__ float g_dinv[N_NODES];
__device__ __nv_bfloat16 g_Ahi[(size_t)N_PAD * D];
__device__ __nv_bfloat16 g_Alo[(size_t)N_PAD * D];
__device__ __nv_bfloat16 g_Bhi[5 * D * D];   // 4 conv layers + post_w, [n][k] K-major
__device__ __nv_bfloat16 g_Blo[5 * D * D];
// CSR (by destination): packed {src, coef_bits}
__device__ int   g_cnt    [N_NODES];
__device__ int   g_rowptr [N_NODES + 1];
__device__ int   g_cursor [N_NODES];
__device__ int   g_blksum [NB_SCAN];
__device__ int2  g_csr    [E_EDGES];

// ---------------- small helpers ----------------
__device__ __forceinline__ float gelu_exact(float x) {
    return 0.5f * x * (1.0f + erff(x * 0.70710678118654752440f));
}
__device__ __forceinline__ void mma_bf16(float* c, const uint32_t* a, const uint32_t* b) {
    asm volatile("mma.sync.aligned.m16n8k16.row.col.f32.bf16.bf16.f32 "
                 "{%0,%1,%2,%3}, {%4,%5,%6,%7}, {%8,%9}, {%0,%1,%2,%3};"
                 : "+f"(c[0]), "+f"(c[1]), "+f"(c[2]), "+f"(c[3])
                 : "r"(a[0]), "r"(a[1]), "r"(a[2]), "r"(a[3]),
                   "r"(b[0]), "r"(b[1]));
}
__device__ __forceinline__ uint32_t smem_u32(const void* p) {
    uint32_t a;
    asm("{ .reg .u64 t; cvta.to.shared.u64 t, %1; cvt.u32.u64 %0, t; }" : "=r"(a) : "l"(p));
    return a;
}
#define LDSM_X4(r0, r1, r2, r3, addr) \
    asm volatile("ldmatrix.sync.aligned.m8n8.x4.shared.b16 {%0,%1,%2,%3}, [%4];" \
                 : "=r"(r0), "=r"(r1), "=r"(r2), "=r"(r3) : "r"(addr))

// ---------------- degree + count ----------------
__global__ void k_deg_init(float* __restrict__ deg, int* __restrict__ cnt) {
    int i = blockIdx.x * blockDim.x + threadIdx.x;
    if (i < N_NODES) { deg[i] = 1.0f; cnt[i] = 0; }
}
__global__ void k_deg_count(const int* __restrict__ ei, const float* __restrict__ ew,
                            float* __restrict__ deg, int* __restrict__ cnt) {
    int e = blockIdx.x * blockDim.x + threadIdx.x;
    if (e < E_EDGES) {
        int dst = ei[E_EDGES + e];
        atomicAdd(&deg[dst], ew[e]);
        atomicAdd(&cnt[dst], 1);
    }
}

// ---------------- CSR: 2-level exclusive scan ----------------
__global__ void k_scan_block(const int* __restrict__ cnt, int* __restrict__ row_ptr,
                             int* __restrict__ blk_sum) {
    __shared__ int wsum[8];
    int i = blockIdx.x * 256 + threadIdx.x;
    int lane = threadIdx.x & 31, wid = threadIdx.x >> 5;
    int v = (i < N_NODES) ? cnt[i] : 0;
    int x = v;
    #pragma unroll
    for (int o = 1; o < 32; o <<= 1) {
        int y = __shfl_up_sync(0xffffffffu, x, o);
        if (lane >= o) x += y;
    }
    if (lane == 31) wsum[wid] = x;
    __syncthreads();
    if (wid == 0) {
        int s = (lane < 8) ? wsum[lane] : 0;
        #pragma unroll
        for (int o = 1; o < 8; o <<= 1) {
            int y = __shfl_up_sync(0xffffffffu, s, o);
            if (lane >= o) s += y;
        }
        if (lane < 8) wsum[lane] = s;   // inclusive warp totals
    }
    __syncthreads();
    int base = (wid > 0) ? wsum[wid - 1] : 0;
    if (i < N_NODES) row_ptr[i] = base + x - v;     // block-local exclusive
    if (threadIdx.x == 255) blk_sum[blockIdx.x] = base + x;  // block total
}
__global__ void k_scan_tops(int* __restrict__ blk_sum) {
    __shared__ int wsum[8];
    int tid = threadIdx.x;
    int lane = tid & 31, wid = tid >> 5;
    int v = (tid < NB_SCAN) ? blk_sum[tid] : 0;
    int x = v;
    #pragma unroll
    for (int o = 1; o < 32; o <<= 1) {
        int y = __shfl_up_sync(0xffffffffu, x, o);
        if (lane >= o) x += y;
    }
    if (lane == 31) wsum[wid] = x;
    __syncthreads();
    if (wid == 0) {
        int s = (lane < 8) ? wsum[lane] : 0;
        #pragma unroll
        for (int o = 1; o < 8; o <<= 1) {
            int y = __shfl_up_sync(0xffffffffu, s, o);
            if (lane >= o) s += y;
        }
        if (lane < 8) wsum[lane] = s;
    }
    __syncthreads();
    int base = (wid > 0) ? wsum[wid - 1] : 0;
    if (tid < NB_SCAN) blk_sum[tid] = base + x - v;  // exclusive block offsets
}
// finalize row_ptr, cursor AND dinv (deg is ready by this point)
__global__ void k_scan_final(int* __restrict__ row_ptr, const int* __restrict__ blk_sum,
                             int* __restrict__ cursor, const float* __restrict__ deg,
                             float* __restrict__ dinv) {
    int i = blockIdx.x * blockDim.x + threadIdx.x;
    if (i < N_NODES) {
        int r = row_ptr[i] + blk_sum[i >> 8];
        row_ptr[i] = r;
        cursor[i] = r;
        dinv[i] = rsqrtf(fmaxf(deg[i], 1e-12f));
    }
    if (i == 0) row_ptr[N_NODES] = E_EDGES;
}
__global__ void k_fill(const int* __restrict__ ei, const float* __restrict__ ew,
                       const float* __restrict__ dinv, int* __restrict__ cursor,
                       int2* __restrict__ csr) {
    int e = blockIdx.x * blockDim.x + threadIdx.x;
    if (e >= E_EDGES) return;
    int src = ei[e];
    int dst = ei[E_EDGES + e];
    int pos = atomicAdd(&cursor[dst], 1);
    float coef = dinv[src] * ew[e] * dinv[dst];
    csr[pos] = make_int2(src, __float_as_int(coef));
}

// ---------------- LayerNorm fused with bf16 hi/lo split: one warp per node ----
__global__ void k_ln_split(const float* __restrict__ h, const float* __restrict__ w,
                           const float* __restrict__ b,
                           __nv_bfloat16* __restrict__ Ahi,
                           __nv_bfloat16* __restrict__ Alo) {
    int gtid = blockIdx.x * blockDim.x + threadIdx.x;
    int node = gtid >> 5;
    int lane = threadIdx.x & 31;
    if (node >= N_NODES) return;

    const float4* hp = (const float4*)(h + (size_t)node * D);
    float4 v0 = hp[lane * 2 + 0];
    float4 v1 = hp[lane * 2 + 1];

    float s = v0.x + v0.y + v0.z + v0.w + v1.x + v1.y + v1.z + v1.w;
    #pragma unroll
    for (int o = 16; o; o >>= 1) s += __shfl_xor_sync(0xffffffffu, s, o);
    float mu = s * (1.0f / 256.0f);

    float dd[8] = {v0.x - mu, v0.y - mu, v0.z - mu, v0.w - mu,
                   v1.x - mu, v1.y - mu, v1.z - mu, v1.w - mu};
    float q = 0.f;
    #pragma unroll
    for (int j = 0; j < 8; j++) q += dd[j] * dd[j];
    #pragma unroll
    for (int o = 16; o; o >>= 1) q += __shfl_xor_sync(0xffffffffu, q, o);
    float rs = rsqrtf(q * (1.0f / 256.0f) + 1e-5f);

    const float4* wp = (const float4*)w;
    const float4* bp = (const float4*)b;
    float4 w0 = wp[lane * 2 + 0], w1 = wp[lane * 2 + 1];
    float4 b0 = bp[lane * 2 + 0], b1 = bp[lane * 2 + 1];
    float ww[8] = {w0.x, w0.y, w0.z, w0.w, w1.x, w1.y, w1.z, w1.w};
    float bb[8] = {b0.x, b0.y, b0.z, b0.w, b1.x, b1.y, b1.z, b1.w};

    __align__(16) __nv_bfloat16 hi[8];
    __align__(16) __nv_bfloat16 lo[8];
    #pragma unroll
    for (int j = 0; j < 8; j++) {
        float o = fmaf(dd[j] * rs, ww[j], bb[j]);
        hi[j] = __float2bfloat16(o);
        lo[j] = __float2bfloat16(o - __bfloat162float(hi[j]));
    }
    *(uint4*)&Ahi[(size_t)node * D + lane * 8] = *(uint4*)hi;
    *(uint4*)&Alo[(size_t)node * D + lane * 8] = *(uint4*)lo;
}

// ---------------- weight transpose + split for all 5 matrices ----------------
__global__ void k_split_B(const float* __restrict__ conv_w, const float* __restrict__ post_w,
                          __nv_bfloat16* __restrict__ bhi,
                          __nv_bfloat16* __restrict__ blo) {
    int idx = blockIdx.x * blockDim.x + threadIdx.x;
    if (idx >= 5 * D * D) return;
    int m = idx / (D * D);
    int rem = idx - m * D * D;
    int n = rem >> 8;
    int k = rem & 255;
    const float* w = (m < 4) ? (conv_w + (size_t)m * D * D) : post_w;
    float v = w[(size_t)k * D + n];
    __nv_bfloat16 hi = __float2bfloat16(v);
    bhi[idx] = hi;
    blo[idx] = __float2bfloat16(v - __bfloat162float(hi));
}

// ---------------- HMMA GEMM: C[M,256] = A[M,256]*B^T + bias, bf16x3 split ----
// One CTA per 128-row band. A (hi+lo, full K=256) staged ONCE in smem;
// four 64-column passes restage only B. 8 warps (4m x 2n), warp tile 32x32.
// Fragment loads via ldmatrix.x4. Optionally writes fp16 mirror Ch.
#define BM 128
#define BNP 64                // columns per pass
#define NPASS (D / BNP)       // 4
#define ASTR 264              // row stride in bf16 (528B = 132 words; 132%32=4)

#define SA_HI 0
#define SA_LO (BM * ASTR * 2)                        // 67584
#define SB_HI (2 * BM * ASTR * 2)                    // 135168
#define SB_LO (2 * BM * ASTR * 2 + BNP * ASTR * 2)   // 168960
#define SM_GEMM (2 * BM * ASTR * 2 + 2 * BNP * ASTR * 2)   // 202752

__global__ void __launch_bounds__(256, 1)
k_gemm_mma(const __nv_bfloat16* __restrict__ Ahi, const __nv_bfloat16* __restrict__ Alo,
           const __nv_bfloat16* __restrict__ Bhi, const __nv_bfloat16* __restrict__ Blo,
           const float* __restrict__ bias, float* __restrict__ C,
           __half* __restrict__ Ch, int Mstore) {
    extern __shared__ char smem[];
    __nv_bfloat16* sAhi = (__nv_bfloat16*)(smem + SA_HI);
    __nv_bfloat16* sAlo = (__nv_bfloat16*)(smem + SA_LO);
    __nv_bfloat16* sBhi = (__nv_bfloat16*)(smem + SB_HI);
    __nv_bfloat16* sBlo = (__nv_bfloat16*)(smem + SB_LO);

    int tid = threadIdx.x;
    int lane = tid & 31;
    int wid = tid >> 5;          // 0..7
    int wrow = wid & 3;          // 0..3 -> 32-row band
    int wcol = wid >> 2;         // 0..1 -> 32-col band (within 64-col pass)
    int row0 = blockIdx.x * BM;

    int lr = lane >> 2;
    int lc = (lane & 3) * 2;

    // ldmatrix per-lane addressing
    int g  = lane >> 3;
    int rg = lane & 7;
    uint32_t offA[2];
    #pragma unroll
    for (int mt = 0; mt < 2; mt++)
        offA[mt] = (uint32_t)(((wrow * 32 + mt * 16 + (g & 1) * 8 + rg) * ASTR
                               + (g >> 1) * 8) * 2);
    uint32_t offB[2];
    #pragma unroll
    for (int ntp = 0; ntp < 2; ntp++)
        offB[ntp] = (uint32_t)(((wcol * 32 + ntp * 16 + (g >> 1) * 8 + rg) * ASTR
                                + (g & 1) * 8) * 2);

    uint32_t aU32[2] = { smem_u32(sAhi), smem_u32(sAlo) };
    uint32_t bU32[2] = { smem_u32(sBhi), smem_u32(sBlo) };

    // ---- stage A (hi+lo), full K=256 ----
    #pragma unroll
    for (int i = 0; i < 16; i++) {
        int idx = tid + i * 256;
        int r = idx >> 5;
        int c = (idx & 31) * 8;
        size_t gg = (size_t)(row0 + r) * D + c;
        *(uint4*)&sAhi[r * ASTR + c] = *(const uint4*)&Ahi[gg];
        *(uint4*)&sAlo[r * ASTR + c] = *(const uint4*)&Alo[gg];
    }

    #pragma unroll
    for (int pass = 0; pass < NPASS; pass++) {
        int col0 = pass * BNP;
        __syncthreads();
        #pragma unroll
        for (int i = 0; i < 8; i++) {
            int idx = tid + i * 256;
            int r = idx >> 5;
            int c = (idx & 31) * 8;
            size_t gg = (size_t)(col0 + r) * D + c;
            *(uint4*)&sBhi[r * ASTR + c] = *(const uint4*)&Bhi[gg];
            *(uint4*)&sBlo[r * ASTR + c] = *(const uint4*)&Blo[gg];
        }
        __syncthreads();

        float acc[2][4][4];
        #pragma unroll
        for (int mt = 0; mt < 2; mt++)
            #pragma unroll
            for (int nt = 0; nt < 4; nt++)
                #pragma unroll
                for (int j = 0; j < 4; j++) acc[mt][nt][j] = 0.0f;

        #pragma unroll
        for (int p = 0; p < 3; p++) {
            uint32_t aB = aU32[(p == 2) ? 1 : 0];
            uint32_t bB = bU32[(p == 1) ? 1 : 0];
            #pragma unroll
            for (int ks = 0; ks < 16; ks++) {
                uint32_t ka = (uint32_t)(ks * 16 * 2);
                uint32_t afr[2][4];
                LDSM_X4(afr[0][0], afr[0][1], afr[0][2], afr[0][3], aB + offA[0] + ka);
                LDSM_X4(afr[1][0], afr[1][1], afr[1][2], afr[1][3], aB + offA[1] + ka);
                uint32_t bfr[4][2];
                LDSM_X4(bfr[0][0], bfr[0][1], bfr[1][0], bfr[1][1], bB + offB[0] + ka);
                LDSM_X4(bfr[2][0], bfr[2][1], bfr[3][0], bfr[3][1], bB + offB[1] + ka);
                #pragma unroll
                for (int mt = 0; mt < 2; mt++)
                    #pragma unroll
                    for (int nt = 0; nt < 4; nt++)
                        mma_bf16(acc[mt][nt], afr[mt], bfr[nt]);
            }
        }

        // ---- epilogue for this pass ----
        #pragma unroll
        for (int mt = 0; mt < 2; mt++) {
            int r0 = row0 + wrow * 32 + mt * 16 + lr;
            #pragma unroll
            for (int nt = 0; nt < 4; nt++) {
                int cc = col0 + wcol * 32 + nt * 8 + lc;
                float bx = 0.f, by = 0.f;
                if (bias) { bx = bias[cc]; by = bias[cc + 1]; }
                if (r0 < Mstore) {
                    float2 o = make_float2(acc[mt][nt][0] + bx, acc[mt][nt][1] + by);
                    *(float2*)&C[(size_t)r0 * D + cc] = o;
                    if (Ch) *(__half2*)&Ch[(size_t)r0 * D + cc] = __floats2half2_rn(o.x, o.y);
                }
                if (r0 + 8 < Mstore) {
                    float2 o = make_float2(acc[mt][nt][2] + bx, acc[mt][nt][3] + by);
                    *(float2*)&C[(size_t)(r0 + 8) * D + cc] = o;
                    if (Ch) *(__half2*)&Ch[(size_t)(r0 + 8) * D + cc] = __floats2half2_rn(o.x, o.y);
                }
            }
        }
    }
}

// ---------------- fused aggregate + GELU + residual + next-layer LN/split ----
// h_out[dst] = h_in[dst] + gelu( conv_b + dinv^2*zw[dst] + sum coef*zwh[src] )
// Neighbor gather uses fp16 mirror (half traffic); self term stays fp32.
__global__ void __launch_bounds__(256)
k_agg_fused(const int* __restrict__ row_ptr, const int2* __restrict__ csr,
            const float* __restrict__ zw, const __half* __restrict__ zwh,
            const float* __restrict__ bias, const float* __restrict__ dinv,
            const float* __restrict__ h_in, float* __restrict__ h_out,
            const float* __restrict__ lnw, const float* __restrict__ lnb,
            __nv_bfloat16* __restrict__ Ahi, __nv_bfloat16* __restrict__ Alo,
            int do_ln) {
    int gtid = blockIdx.x * blockDim.x + threadIdx.x;
    int node = gtid >> 5;
    int lane = threadIdx.x & 31;
    if (node >= N_NODES) return;

    int beg = row_ptr[node];
    int end = row_ptr[node + 1];
    float s = dinv[node];
    s = s * s;

    const float4* zp = (const float4*)(zw + (size_t)node * D) + lane * 2;
    float4 z0 = zp[0], z1 = zp[1];
    const float4* bp = (const float4*)bias + lane * 2;
    float4 b0 = bp[0], b1 = bp[1];

    float acc[8];
    acc[0] = fmaf(s, z0.x, b0.x); acc[1] = fmaf(s, z0.y, b0.y);
    acc[2] = fmaf(s, z0.z, b0.z); acc[3] = fmaf(s, z0.w, b0.w);
    acc[4] = fmaf(s, z1.x, b1.x); acc[5] = fmaf(s, z1.y, b1.y);
    acc[6] = fmaf(s, z1.z, b1.z); acc[7] = fmaf(s, z1.w, b1.w);

    int e = beg;
    for (; e + 4 <= end; e += 4) {
        int2 e1 = csr[e], e2 = csr[e + 1], e3 = csr[e + 2], e4 = csr[e + 3];
        float c1 = __int_as_float(e1.y), c2 = __int_as_float(e2.y);
        float c3 = __int_as_float(e3.y), c4 = __int_as_float(e4.y);
        uint4 q1 = *((const uint4*)(zwh + (size_t)e1.x * D) + lane);
        uint4 q2 = *((const uint4*)(zwh + (size_t)e2.x * D) + lane);
        uint4 q3 = *((const uint4*)(zwh + (size_t)e3.x * D) + lane);
        uint4 q4 = *((const uint4*)(zwh + (size_t)e4.x * D) + lane);
        const __half2* f1 = (const __half2*)&q1;
        const __half2* f2 = (const __half2*)&q2;
        const __half2* f3 = (const __half2*)&q3;
        const __half2* f4 = (const __half2*)&q4;
        #pragma unroll
        for (int j = 0; j < 4; j++) {
            float2 u = __half22float2(f1[j]);
            acc[j * 2 + 0] = fmaf(c1, u.x, acc[j * 2 + 0]);
            acc[j * 2 + 1] = fmaf(c1, u.y, acc[j * 2 + 1]);
        }
        #pragma unroll
        for (int j = 0; j < 4; j++) {
            float2 u = __half22float2(f2[j]);
            acc[j * 2 + 0] = fmaf(c2, u.x, acc[j * 2 + 0]);
            acc[j * 2 + 1] = fmaf(c2, u.y, acc[j * 2 + 1]);
        }
        #pragma unroll
        for (int j = 0; j < 4; j++) {
            float2 u = __half22float2(f3[j]);
            acc[j * 2 + 0] = fmaf(c3, u.x, acc[j * 2 + 0]);
            acc[j * 2 + 1] = fmaf(c3, u.y, acc[j * 2 + 1]);
        }
        #pragma unroll
        for (int j = 0; j < 4; j++) {
            float2 u = __half22float2(f4[j]);
            acc[j * 2 + 0] = fmaf(c4, u.x, acc[j * 2 + 0]);
            acc[j * 2 + 1] = fmaf(c4, u.y, acc[j * 2 + 1]);
        }
    }
    for (; e < end; e++) {
        int2 e1 = csr[e];
        float c1 = __int_as_float(e1.y);
        uint4 q1 = *((const uint4*)(zwh + (size_t)e1.x * D) + lane);
        const __half2* f1 = (const __half2*)&q1;
        #pragma unroll
        for (int j = 0; j < 4; j++) {
            float2 u = __half22float2(f1[j]);
            acc[j * 2 + 0] = fmaf(c1, u.x, acc[j * 2 + 0]);
            acc[j * 2 + 1] = fmaf(c1, u.y, acc[j * 2 + 1]);
        }
    }

    // residual (read h_in, write h_out)
    const float4* hip = (const float4*)(h_in + (size_t)node * D) + lane * 2;
    float4 h0 = hip[0], h1 = hip[1];
    float hv[8];
    hv[0] = h0.x + gelu_exact(acc[0]); hv[1] = h0.y + gelu_exact(acc[1]);
    hv[2] = h0.z + gelu_exact(acc[2]); hv[3] = h0.w + gelu_exact(acc[3]);
    hv[4] = h1.x + gelu_exact(acc[4]); hv[5] = h1.y + gelu_exact(acc[5]);
    hv[6] = h1.z + gelu_exact(acc[6]); hv[7] = h1.w + gelu_exact(acc[7]);
    float4* hop = (float4*)(h_out + (size_t)node * D) + lane * 2;
    hop[0] = make_float4(hv[0], hv[1], hv[2], hv[3]);
    hop[1] = make_float4(hv[4], hv[5], hv[6], hv[7]);

    // next-layer LN (or identity) + bf16 hi/lo split
    float ov[8];
    if (do_ln) {
        float sum = hv[0] + hv[1] + hv[2] + hv[3] + hv[4] + hv[5] + hv[6] + hv[7];
        #pragma unroll
        for (int o = 16; o; o >>= 1) sum += __shfl_xor_sync(0xffffffffu, sum, o);
        float mu = sum * (1.0f / 256.0f);
        float q = 0.f;
        #pragma unroll
        for (int j = 0; j < 8; j++) { float d = hv[j] - mu; q += d * d; }
        #pragma unroll
        for (int o = 16; o; o >>= 1) q += __shfl_xor_sync(0xffffffffu, q, o);
        float rsg = rsqrtf(q * (1.0f / 256.0f) + 1e-5f);

        const float4* wp = (const float4*)lnw + lane * 2;
        const float4* lbp = (const float4*)lnb + lane * 2;
        float4 w0 = wp[0], w1 = wp[1];
        float4 lb0 = lbp[0], lb1 = lbp[1];
        float ww[8] = {w0.x, w0.y, w0.z, w0.w, w1.x, w1.y, w1.z, w1.w};
        float bb2[8] = {lb0.x, lb0.y, lb0.z, lb0.w, lb1.x, lb1.y, lb1.z, lb1.w};
        #pragma unroll
        for (int j = 0; j < 8; j++)
            ov[j] = fmaf((hv[j] - mu) * rsg, ww[j], bb2[j]);
    } else {
        #pragma unroll
        for (int j = 0; j < 8; j++) ov[j] = hv[j];
    }

    __align__(16) __nv_bfloat16 hi[8];
    __align__(16) __nv_bfloat16 lo[8];
    #pragma unroll
    for (int j = 0; j < 8; j++) {
        hi[j] = __float2bfloat16(ov[j]);
        lo[j] = __float2bfloat16(ov[j] - __bfloat162float(hi[j]));
    }
    *(uint4*)&Ahi[(size_t)node * D + lane * 8] = *(uint4*)hi;
    *(uint4*)&Alo[(size_t)node * D + lane * 8] = *(uint4*)lo;
}

// ---------------- launch ----------------
extern "C" void kernel_launch(void* const* d_in, const int* in_sizes, int n_in,
                              void* d_out, int out_size) {
    const int*   ei     = (const int*)  d_in[1];
    const float* ew     = (const float*)d_in[2];
    const float* emb    = (const float*)d_in[3];
    const float* ln_w   = (const float*)d_in[4];
    const float* ln_b   = (const float*)d_in[5];
    const float* conv_w = (const float*)d_in[6];
    const float* conv_b = (const float*)d_in[7];
    const float* post_w = (const float*)d_in[8];
    const float* post_b = (const float*)d_in[9];
    float* out = (float*)d_out;

    float *h, *zw, *deg, *dinv;
    __half *zwh;
    int *cnt, *rowptr, *cursor, *blksum;
    int2 *csr;
    __nv_bfloat16 *Ahi, *Alo, *Bhi, *Blo;
    cudaGetSymbolAddress((void**)&h,    g_h);
    cudaGetSymbolAddress((void**)&zw,   g_zw);
    cudaGetSymbolAddress((void**)&zwh,  g_zwh);
    cudaGetSymbolAddress((void**)&deg,  g_deg);
    cudaGetSymbolAddress((void**)&dinv, g_dinv);
    cudaGetSymbolAddress((void**)&Ahi,  g_Ahi);
    cudaGetSymbolAddress((void**)&Alo,  g_Alo);
    cudaGetSymbolAddress((void**)&Bhi,  g_Bhi);
    cudaGetSymbolAddress((void**)&Blo,  g_Blo);
    cudaGetSymbolAddress((void**)&cnt,     g_cnt);
    cudaGetSymbolAddress((void**)&rowptr,  g_rowptr);
    cudaGetSymbolAddress((void**)&cursor,  g_cursor);
    cudaGetSymbolAddress((void**)&blksum,  g_blksum);
    cudaGetSymbolAddress((void**)&csr,     g_csr);

    cudaFuncSetAttribute(k_gemm_mma, cudaFuncAttributeMaxDynamicSharedMemorySize, SM_GEMM);

    // degree + counts
    k_deg_init <<<(N_NODES + 255) / 256, 256>>>(deg, cnt);
    k_deg_count<<<(E_EDGES + 255) / 256, 256>>>(ei, ew, deg, cnt);

    // CSR build (k_scan_final also computes dinv)
    k_scan_block<<<NB_SCAN, 256>>>(cnt, rowptr, blksum);
    k_scan_tops <<<1, 256>>>(blksum);
    k_scan_final<<<(N_NODES + 255) / 256, 256>>>(rowptr, blksum, cursor, deg, dinv);
    k_fill      <<<(E_EDGES + 255) / 256, 256>>>(ei, ew, dinv, cursor, csr);

    // split + transpose all 5 weight matrices in one kernel
    k_split_B<<<(5 * D * D + 255) / 256, 256>>>(conv_w, post_w, Bhi, Blo);

    // LN for layer 0 reads emb directly (no h=emb copy needed)
    k_ln_split<<<(N_NODES * 32 + 255) / 256, 256>>>(emb, ln_w, ln_b, Ahi, Alo);

    int gemm_grid = N_PAD / BM;   // 391 CTAs, one per 128-row band

    for (int i = 0; i < L; i++) {
        k_gemm_mma<<<gemm_grid, 256, SM_GEMM>>>(Ahi, Alo,
                                                Bhi + (size_t)i * D * D,
                                                Blo + (size_t)i * D * D,
                                                nullptr, zw, zwh, N_PAD);
        const float* nlw = ln_w + (size_t)(i + 1) * D;
        const float* nlb = ln_b + (size_t)(i + 1) * D;
        int do_ln = (i < L - 1) ? 1 : 0;
        if (!do_ln) { nlw = ln_w; nlb = ln_b; }
        const float* h_in = (i == 0) ? emb : h;
        k_agg_fused<<<(N_NODES * 32 + 255) / 256, 256>>>(rowptr, csr,
                                                         zw, zwh,
                                                         conv_b + (size_t)i * D,
                                                         dinv, h_in, h, nlw, nlb,
                                                         Ahi, Alo, do_ln);
    }

    // final projection (no fp16 mirror needed)
    k_gemm_mma<<<gemm_grid, 256, SM_GEMM>>>(Ahi, Alo,
                                            Bhi + (size_t)4 * D * D,
                                            Blo + (size_t)4 * D * D,
                                            post_b, out, nullptr, N_NODES);
}

// round 15
// speedup vs baseline: 1.4460x; 1.4460x over previous
#include <cuda_runtime.h>
#include <cuda_bf16.h>
#include <cuda_fp16.h>
#include <math.h>
#include <stdint.h>

#define N_NODES 50000
#define N_PAD   50048          // multiple of 128 for GEMM tiles
#define E_EDGES 800000
#define D       256
#define L       4
#define NB_SCAN 196            // ceil(N_NODES/256)

// ---------------- scratch (device globals; .bss zero-init, pads stay 0) ----
__device__ float g_h  [(size_t)N_PAD * D];
__device__ float g_zw [(size_t)N_PAD * D];
__device__ __half g_zwh[(size_t)N_PAD * D];   // fp16 mirror for neighbor gather
__device__ float g_deg [N_NODES];
__device__ float g_dinv[N_NODES];
__device__ __nv_bfloat16 g_Ahi[(size_t)N_PAD * D];
__device__ __nv_bfloat16 g_Alo[(size_t)N_PAD * D];
__device__ __nv_bfloat16 g_Bhi[5 * D * D];   // 4 conv layers + post_w, [n][k] K-major
__device__ __nv_bfloat16 g_Blo[5 * D * D];
// CSR (by destination): packed {src, coef_bits}
__device__ int   g_cnt    [N_NODES];
__device__ int   g_rowptr [N_NODES + 1];
__device__ int   g_cursor [N_NODES];
__device__ int   g_blksum [NB_SCAN];
__device__ int2  g_csr    [E_EDGES];

// ---------------- small helpers ----------------
__device__ __forceinline__ float gelu_exact(float x) {
    return 0.5f * x * (1.0f + erff(x * 0.70710678118654752440f));
}
__device__ __forceinline__ void mma_bf16(float* c, const uint32_t* a, const uint32_t* b) {
    asm volatile("mma.sync.aligned.m16n8k16.row.col.f32.bf16.bf16.f32 "
                 "{%0,%1,%2,%3}, {%4,%5,%6,%7}, {%8,%9}, {%0,%1,%2,%3};"
                 : "+f"(c[0]), "+f"(c[1]), "+f"(c[2]), "+f"(c[3])
                 : "r"(a[0]), "r"(a[1]), "r"(a[2]), "r"(a[3]),
                   "r"(b[0]), "r"(b[1]));
}
__device__ __forceinline__ uint32_t smem_u32(const void* p) {
    uint32_t a;
    asm("{ .reg .u64 t; cvta.to.shared.u64 t, %1; cvt.u32.u64 %0, t; }" : "=r"(a) : "l"(p));
    return a;
}
#define LDSM_X4(r0, r1, r2, r3, addr) \
    asm volatile("ldmatrix.sync.aligned.m8n8.x4.shared.b16 {%0,%1,%2,%3}, [%4];" \
                 : "=r"(r0), "=r"(r1), "=r"(r2), "=r"(r3) : "r"(addr))

// Convert packed fp16 pair (as uint32) to float2 WITHOUT any address-of
// (avoids local-memory demotion; ptxas folds into F2F.F32.F16 half-selects).
__device__ __forceinline__ float2 h2_to_f2(uint32_t w) {
    __half2_raw r;
    r.x = (unsigned short)(w & 0xffffu);
    r.y = (unsigned short)(w >> 16);
    return __half22float2((__half2)r);
}
// accumulate 8 features from a uint4 of 8 halves, scaled by c
__device__ __forceinline__ void acc_h8(float* acc, uint4 q, float c) {
    float2 u;
    u = h2_to_f2(q.x); acc[0] = fmaf(c, u.x, acc[0]); acc[1] = fmaf(c, u.y, acc[1]);
    u = h2_to_f2(q.y); acc[2] = fmaf(c, u.x, acc[2]); acc[3] = fmaf(c, u.y, acc[3]);
    u = h2_to_f2(q.z); acc[4] = fmaf(c, u.x, acc[4]); acc[5] = fmaf(c, u.y, acc[5]);
    u = h2_to_f2(q.w); acc[6] = fmaf(c, u.x, acc[6]); acc[7] = fmaf(c, u.y, acc[7]);
}

// ---------------- degree + count ----------------
__global__ void k_deg_init(float* __restrict__ deg, int* __restrict__ cnt) {
    int i = blockIdx.x * blockDim.x + threadIdx.x;
    if (i < N_NODES) { deg[i] = 1.0f; cnt[i] = 0; }
}
__global__ void k_deg_count(const int* __restrict__ ei, const float* __restrict__ ew,
                            float* __restrict__ deg, int* __restrict__ cnt) {
    int e = blockIdx.x * blockDim.x + threadIdx.x;
    if (e < E_EDGES) {
        int dst = ei[E_EDGES + e];
        atomicAdd(&deg[dst], ew[e]);
        atomicAdd(&cnt[dst], 1);
    }
}

// ---------------- CSR: 2-level exclusive scan ----------------
__global__ void k_scan_block(const int* __restrict__ cnt, int* __restrict__ row_ptr,
                             int* __restrict__ blk_sum) {
    __shared__ int wsum[8];
    int i = blockIdx.x * 256 + threadIdx.x;
    int lane = threadIdx.x & 31, wid = threadIdx.x >> 5;
    int v = (i < N_NODES) ? cnt[i] : 0;
    int x = v;
    #pragma unroll
    for (int o = 1; o < 32; o <<= 1) {
        int y = __shfl_up_sync(0xffffffffu, x, o);
        if (lane >= o) x += y;
    }
    if (lane == 31) wsum[wid] = x;
    __syncthreads();
    if (wid == 0) {
        int s = (lane < 8) ? wsum[lane] : 0;
        #pragma unroll
        for (int o = 1; o < 8; o <<= 1) {
            int y = __shfl_up_sync(0xffffffffu, s, o);
            if (lane >= o) s += y;
        }
        if (lane < 8) wsum[lane] = s;   // inclusive warp totals
    }
    __syncthreads();
    int base = (wid > 0) ? wsum[wid - 1] : 0;
    if (i < N_NODES) row_ptr[i] = base + x - v;     // block-local exclusive
    if (threadIdx.x == 255) blk_sum[blockIdx.x] = base + x;  // block total
}
__global__ void k_scan_tops(int* __restrict__ blk_sum) {
    __shared__ int wsum[8];
    int tid = threadIdx.x;
    int lane = tid & 31, wid = tid >> 5;
    int v = (tid < NB_SCAN) ? blk_sum[tid] : 0;
    int x = v;
    #pragma unroll
    for (int o = 1; o < 32; o <<= 1) {
        int y = __shfl_up_sync(0xffffffffu, x, o);
        if (lane >= o) x += y;
    }
    if (lane == 31) wsum[wid] = x;
    __syncthreads();
    if (wid == 0) {
        int s = (lane < 8) ? wsum[lane] : 0;
        #pragma unroll
        for (int o = 1; o < 8; o <<= 1) {
            int y = __shfl_up_sync(0xffffffffu, s, o);
            if (lane >= o) s += y;
        }
        if (lane < 8) wsum[lane] = s;
    }
    __syncthreads();
    int base = (wid > 0) ? wsum[wid - 1] : 0;
    if (tid < NB_SCAN) blk_sum[tid] = base + x - v;  // exclusive block offsets
}
// finalize row_ptr, cursor AND dinv (deg is ready by this point)
__global__ void k_scan_final(int* __restrict__ row_ptr, const int* __restrict__ blk_sum,
                             int* __restrict__ cursor, const float* __restrict__ deg,
                             float* __restrict__ dinv) {
    int i = blockIdx.x * blockDim.x + threadIdx.x;
    if (i < N_NODES) {
        int r = row_ptr[i] + blk_sum[i >> 8];
        row_ptr[i] = r;
        cursor[i] = r;
        dinv[i] = rsqrtf(fmaxf(deg[i], 1e-12f));
    }
    if (i == 0) row_ptr[N_NODES] = E_EDGES;
}
__global__ void k_fill(const int* __restrict__ ei, const float* __restrict__ ew,
                       const float* __restrict__ dinv, int* __restrict__ cursor,
                       int2* __restrict__ csr) {
    int e = blockIdx.x * blockDim.x + threadIdx.x;
    if (e >= E_EDGES) return;
    int src = ei[e];
    int dst = ei[E_EDGES + e];
    int pos = atomicAdd(&cursor[dst], 1);
    float coef = dinv[src] * ew[e] * dinv[dst];
    csr[pos] = make_int2(src, __float_as_int(coef));
}

// ---------------- LayerNorm fused with bf16 hi/lo split: one warp per node ----
__global__ void k_ln_split(const float* __restrict__ h, const float* __restrict__ w,
                           const float* __restrict__ b,
                           __nv_bfloat16* __restrict__ Ahi,
                           __nv_bfloat16* __restrict__ Alo) {
    int gtid = blockIdx.x * blockDim.x + threadIdx.x;
    int node = gtid >> 5;
    int lane = threadIdx.x & 31;
    if (node >= N_NODES) return;

    const float4* hp = (const float4*)(h + (size_t)node * D);
    float4 v0 = hp[lane * 2 + 0];
    float4 v1 = hp[lane * 2 + 1];

    float s = v0.x + v0.y + v0.z + v0.w + v1.x + v1.y + v1.z + v1.w;
    #pragma unroll
    for (int o = 16; o; o >>= 1) s += __shfl_xor_sync(0xffffffffu, s, o);
    float mu = s * (1.0f / 256.0f);

    float dd[8] = {v0.x - mu, v0.y - mu, v0.z - mu, v0.w - mu,
                   v1.x - mu, v1.y - mu, v1.z - mu, v1.w - mu};
    float q = 0.f;
    #pragma unroll
    for (int j = 0; j < 8; j++) q += dd[j] * dd[j];
    #pragma unroll
    for (int o = 16; o; o >>= 1) q += __shfl_xor_sync(0xffffffffu, q, o);
    float rs = rsqrtf(q * (1.0f / 256.0f) + 1e-5f);

    const float4* wp = (const float4*)w;
    const float4* bp = (const float4*)b;
    float4 w0 = wp[lane * 2 + 0], w1 = wp[lane * 2 + 1];
    float4 b0 = bp[lane * 2 + 0], b1 = bp[lane * 2 + 1];
    float ww[8] = {w0.x, w0.y, w0.z, w0.w, w1.x, w1.y, w1.z, w1.w};
    float bb[8] = {b0.x, b0.y, b0.z, b0.w, b1.x, b1.y, b1.z, b1.w};

    __align__(16) __nv_bfloat16 hi[8];
    __align__(16) __nv_bfloat16 lo[8];
    #pragma unroll
    for (int j = 0; j < 8; j++) {
        float o = fmaf(dd[j] * rs, ww[j], bb[j]);
        hi[j] = __float2bfloat16(o);
        lo[j] = __float2bfloat16(o - __bfloat162float(hi[j]));
    }
    *(uint4*)&Ahi[(size_t)node * D + lane * 8] = *(uint4*)hi;
    *(uint4*)&Alo[(size_t)node * D + lane * 8] = *(uint4*)lo;
}

// ---------------- weight transpose + split for all 5 matrices ----------------
__global__ void k_split_B(const float* __restrict__ conv_w, const float* __restrict__ post_w,
                          __nv_bfloat16* __restrict__ bhi,
                          __nv_bfloat16* __restrict__ blo) {
    int idx = blockIdx.x * blockDim.x + threadIdx.x;
    if (idx >= 5 * D * D) return;
    int m = idx / (D * D);
    int rem = idx - m * D * D;
    int n = rem >> 8;
    int k = rem & 255;
    const float* w = (m < 4) ? (conv_w + (size_t)m * D * D) : post_w;
    float v = w[(size_t)k * D + n];
    __nv_bfloat16 hi = __float2bfloat16(v);
    bhi[idx] = hi;
    blo[idx] = __float2bfloat16(v - __bfloat162float(hi));
}

// ---------------- HMMA GEMM: C[M,256] = A[M,256]*B^T + bias, bf16x3 split ----
// One CTA per 128-row band. A (hi+lo, full K=256) staged ONCE in smem;
// four 64-column passes restage only B. 8 warps (4m x 2n), warp tile 32x32.
// Fragment loads via ldmatrix.x4. Optionally writes fp16 mirror Ch.
#define BM 128
#define BNP 64                // columns per pass
#define NPASS (D / BNP)       // 4
#define ASTR 264              // row stride in bf16 (528B = 132 words; 132%32=4)

#define SA_HI 0
#define SA_LO (BM * ASTR * 2)                        // 67584
#define SB_HI (2 * BM * ASTR * 2)                    // 135168
#define SB_LO (2 * BM * ASTR * 2 + BNP * ASTR * 2)   // 168960
#define SM_GEMM (2 * BM * ASTR * 2 + 2 * BNP * ASTR * 2)   // 202752

__global__ void __launch_bounds__(256, 1)
k_gemm_mma(const __nv_bfloat16* __restrict__ Ahi, const __nv_bfloat16* __restrict__ Alo,
           const __nv_bfloat16* __restrict__ Bhi, const __nv_bfloat16* __restrict__ Blo,
           const float* __restrict__ bias, float* __restrict__ C,
           __half* __restrict__ Ch, int Mstore) {
    extern __shared__ char smem[];
    __nv_bfloat16* sAhi = (__nv_bfloat16*)(smem + SA_HI);
    __nv_bfloat16* sAlo = (__nv_bfloat16*)(smem + SA_LO);
    __nv_bfloat16* sBhi = (__nv_bfloat16*)(smem + SB_HI);
    __nv_bfloat16* sBlo = (__nv_bfloat16*)(smem + SB_LO);

    int tid = threadIdx.x;
    int lane = tid & 31;
    int wid = tid >> 5;          // 0..7
    int wrow = wid & 3;          // 0..3 -> 32-row band
    int wcol = wid >> 2;         // 0..1 -> 32-col band (within 64-col pass)
    int row0 = blockIdx.x * BM;

    int lr = lane >> 2;
    int lc = (lane & 3) * 2;

    // ldmatrix per-lane addressing
    int g  = lane >> 3;
    int rg = lane & 7;
    uint32_t offA[2];
    #pragma unroll
    for (int mt = 0; mt < 2; mt++)
        offA[mt] = (uint32_t)(((wrow * 32 + mt * 16 + (g & 1) * 8 + rg) * ASTR
                               + (g >> 1) * 8) * 2);
    uint32_t offB[2];
    #pragma unroll
    for (int ntp = 0; ntp < 2; ntp++)
        offB[ntp] = (uint32_t)(((wcol * 32 + ntp * 16 + (g >> 1) * 8 + rg) * ASTR
                                + (g & 1) * 8) * 2);

    uint32_t aU32[2] = { smem_u32(sAhi), smem_u32(sAlo) };
    uint32_t bU32[2] = { smem_u32(sBhi), smem_u32(sBlo) };

    // ---- stage A (hi+lo), full K=256 ----
    #pragma unroll
    for (int i = 0; i < 16; i++) {
        int idx = tid + i * 256;
        int r = idx >> 5;
        int c = (idx & 31) * 8;
        size_t gg = (size_t)(row0 + r) * D + c;
        *(uint4*)&sAhi[r * ASTR + c] = *(const uint4*)&Ahi[gg];
        *(uint4*)&sAlo[r * ASTR + c] = *(const uint4*)&Alo[gg];
    }

    #pragma unroll
    for (int pass = 0; pass < NPASS; pass++) {
        int col0 = pass * BNP;
        __syncthreads();
        #pragma unroll
        for (int i = 0; i < 8; i++) {
            int idx = tid + i * 256;
            int r = idx >> 5;
            int c = (idx & 31) * 8;
            size_t gg = (size_t)(col0 + r) * D + c;
            *(uint4*)&sBhi[r * ASTR + c] = *(const uint4*)&Bhi[gg];
            *(uint4*)&sBlo[r * ASTR + c] = *(const uint4*)&Blo[gg];
        }
        __syncthreads();

        float acc[2][4][4];
        #pragma unroll
        for (int mt = 0; mt < 2; mt++)
            #pragma unroll
            for (int nt = 0; nt < 4; nt++)
                #pragma unroll
                for (int j = 0; j < 4; j++) acc[mt][nt][j] = 0.0f;

        #pragma unroll
        for (int p = 0; p < 3; p++) {
            uint32_t aB = aU32[(p == 2) ? 1 : 0];
            uint32_t bB = bU32[(p == 1) ? 1 : 0];
            #pragma unroll
            for (int ks = 0; ks < 16; ks++) {
                uint32_t ka = (uint32_t)(ks * 16 * 2);
                uint32_t afr[2][4];
                LDSM_X4(afr[0][0], afr[0][1], afr[0][2], afr[0][3], aB + offA[0] + ka);
                LDSM_X4(afr[1][0], afr[1][1], afr[1][2], afr[1][3], aB + offA[1] + ka);
                uint32_t bfr[4][2];
                LDSM_X4(bfr[0][0], bfr[0][1], bfr[1][0], bfr[1][1], bB + offB[0] + ka);
                LDSM_X4(bfr[2][0], bfr[2][1], bfr[3][0], bfr[3][1], bB + offB[1] + ka);
                #pragma unroll
                for (int mt = 0; mt < 2; mt++)
                    #pragma unroll
                    for (int nt = 0; nt < 4; nt++)
                        mma_bf16(acc[mt][nt], afr[mt], bfr[nt]);
            }
        }

        // ---- epilogue for this pass ----
        #pragma unroll
        for (int mt = 0; mt < 2; mt++) {
            int r0 = row0 + wrow * 32 + mt * 16 + lr;
            #pragma unroll
            for (int nt = 0; nt < 4; nt++) {
                int cc = col0 + wcol * 32 + nt * 8 + lc;
                float bx = 0.f, by = 0.f;
                if (bias) { bx = bias[cc]; by = bias[cc + 1]; }
                if (r0 < Mstore) {
                    float2 o = make_float2(acc[mt][nt][0] + bx, acc[mt][nt][1] + by);
                    *(float2*)&C[(size_t)r0 * D + cc] = o;
                    if (Ch) *(__half2*)&Ch[(size_t)r0 * D + cc] = __floats2half2_rn(o.x, o.y);
                }
                if (r0 + 8 < Mstore) {
                    float2 o = make_float2(acc[mt][nt][2] + bx, acc[mt][nt][3] + by);
                    *(float2*)&C[(size_t)(r0 + 8) * D + cc] = o;
                    if (Ch) *(__half2*)&Ch[(size_t)(r0 + 8) * D + cc] = __floats2half2_rn(o.x, o.y);
                }
            }
        }
    }
}

// ---------------- fused aggregate + GELU + residual + next-layer LN/split ----
// h_out[dst] = h_in[dst] + gelu( conv_b + dinv^2*zw[dst] + sum coef*zwh[src] )
// Neighbor gather from fp16 mirror; conversion is register-only (no address-of).
__global__ void __launch_bounds__(256)
k_agg_fused(const int* __restrict__ row_ptr, const int2* __restrict__ csr,
            const float* __restrict__ zw, const __half* __restrict__ zwh,
            const float* __restrict__ bias, const float* __restrict__ dinv,
            const float* __restrict__ h_in, float* __restrict__ h_out,
            const float* __restrict__ lnw, const float* __restrict__ lnb,
            __nv_bfloat16* __restrict__ Ahi, __nv_bfloat16* __restrict__ Alo,
            int do_ln) {
    int gtid = blockIdx.x * blockDim.x + threadIdx.x;
    int node = gtid >> 5;
    int lane = threadIdx.x & 31;
    if (node >= N_NODES) return;

    int beg = row_ptr[node];
    int end = row_ptr[node + 1];
    float s = dinv[node];
    s = s * s;

    const float4* zp = (const float4*)(zw + (size_t)node * D) + lane * 2;
    float4 z0 = zp[0], z1 = zp[1];
    const float4* bp = (const float4*)bias + lane * 2;
    float4 b0 = bp[0], b1 = bp[1];

    float acc[8];
    acc[0] = fmaf(s, z0.x, b0.x); acc[1] = fmaf(s, z0.y, b0.y);
    acc[2] = fmaf(s, z0.z, b0.z); acc[3] = fmaf(s, z0.w, b0.w);
    acc[4] = fmaf(s, z1.x, b1.x); acc[5] = fmaf(s, z1.y, b1.y);
    acc[6] = fmaf(s, z1.z, b1.z); acc[7] = fmaf(s, z1.w, b1.w);

    int e = beg;
    for (; e + 4 <= end; e += 4) {
        int2 e1 = csr[e], e2 = csr[e + 1], e3 = csr[e + 2], e4 = csr[e + 3];
        float c1 = __int_as_float(e1.y), c2 = __int_as_float(e2.y);
        float c3 = __int_as_float(e3.y), c4 = __int_as_float(e4.y);
        uint4 q1 = *((const uint4*)(zwh + (size_t)e1.x * D) + lane);
        uint4 q2 = *((const uint4*)(zwh + (size_t)e2.x * D) + lane);
        uint4 q3 = *((const uint4*)(zwh + (size_t)e3.x * D) + lane);
        uint4 q4 = *((const uint4*)(zwh + (size_t)e4.x * D) + lane);
        acc_h8(acc, q1, c1);
        acc_h8(acc, q2, c2);
        acc_h8(acc, q3, c3);
        acc_h8(acc, q4, c4);
    }
    for (; e < end; e++) {
        int2 e1 = csr[e];
        float c1 = __int_as_float(e1.y);
        uint4 q1 = *((const uint4*)(zwh + (size_t)e1.x * D) + lane);
        acc_h8(acc, q1, c1);
    }

    // residual (read h_in, write h_out)
    const float4* hip = (const float4*)(h_in + (size_t)node * D) + lane * 2;
    float4 h0 = hip[0], h1 = hip[1];
    float hv[8];
    hv[0] = h0.x + gelu_exact(acc[0]); hv[1] = h0.y + gelu_exact(acc[1]);
    hv[2] = h0.z + gelu_exact(acc[2]); hv[3] = h0.w + gelu_exact(acc[3]);
    hv[4] = h1.x + gelu_exact(acc[4]); hv[5] = h1.y + gelu_exact(acc[5]);
    hv[6] = h1.z + gelu_exact(acc[6]); hv[7] = h1.w + gelu_exact(acc[7]);
    float4* hop = (float4*)(h_out + (size_t)node * D) + lane * 2;
    hop[0] = make_float4(hv[0], hv[1], hv[2], hv[3]);
    hop[1] = make_float4(hv[4], hv[5], hv[6], hv[7]);

    // next-layer LN (or identity) + bf16 hi/lo split
    float ov[8];
    if (do_ln) {
        float sum = hv[0] + hv[1] + hv[2] + hv[3] + hv[4] + hv[5] + hv[6] + hv[7];
        #pragma unroll
        for (int o = 16; o; o >>= 1) sum += __shfl_xor_sync(0xffffffffu, sum, o);
        float mu = sum * (1.0f / 256.0f);
        float q = 0.f;
        #pragma unroll
        for (int j = 0; j < 8; j++) { float d = hv[j] - mu; q += d * d; }
        #pragma unroll
        for (int o = 16; o; o >>= 1) q += __shfl_xor_sync(0xffffffffu, q, o);
        float rsg = rsqrtf(q * (1.0f / 256.0f) + 1e-5f);

        const float4* wp = (const float4*)lnw + lane * 2;
        const float4* lbp = (const float4*)lnb + lane * 2;
        float4 w0 = wp[0], w1 = wp[1];
        float4 lb0 = lbp[0], lb1 = lbp[1];
        float ww[8] = {w0.x, w0.y, w0.z, w0.w, w1.x, w1.y, w1.z, w1.w};
        float bb2[8] = {lb0.x, lb0.y, lb0.z, lb0.w, lb1.x, lb1.y, lb1.z, lb1.w};
        #pragma unroll
        for (int j = 0; j < 8; j++)
            ov[j] = fmaf((hv[j] - mu) * rsg, ww[j], bb2[j]);
    } else {
        #pragma unroll
        for (int j = 0; j < 8; j++) ov[j] = hv[j];
    }

    __align__(16) __nv_bfloat16 hi[8];
    __align__(16) __nv_bfloat16 lo[8];
    #pragma unroll
    for (int j = 0; j < 8; j++) {
        hi[j] = __float2bfloat16(ov[j]);
        lo[j] = __float2bfloat16(ov[j] - __bfloat162float(hi[j]));
    }
    *(uint4*)&Ahi[(size_t)node * D + lane * 8] = *(uint4*)hi;
    *(uint4*)&Alo[(size_t)node * D + lane * 8] = *(uint4*)lo;
}

// ---------------- launch ----------------
extern "C" void kernel_launch(void* const* d_in, const int* in_sizes, int n_in,
                              void* d_out, int out_size) {
    const int*   ei     = (const int*)  d_in[1];
    const float* ew     = (const float*)d_in[2];
    const float* emb    = (const float*)d_in[3];
    const float* ln_w   = (const float*)d_in[4];
    const float* ln_b   = (const float*)d_in[5];
    const float* conv_w = (const float*)d_in[6];
    const float* conv_b = (const float*)d_in[7];
    const float* post_w = (const float*)d_in[8];
    const float* post_b = (const float*)d_in[9];
    float* out = (float*)d_out;

    float *h, *zw, *deg, *dinv;
    __half *zwh;
    int *cnt, *rowptr, *cursor, *blksum;
    int2 *csr;
    __nv_bfloat16 *Ahi, *Alo, *Bhi, *Blo;
    cudaGetSymbolAddress((void**)&h,    g_h);
    cudaGetSymbolAddress((void**)&zw,   g_zw);
    cudaGetSymbolAddress((void**)&zwh,  g_zwh);
    cudaGetSymbolAddress((void**)&deg,  g_deg);
    cudaGetSymbolAddress((void**)&dinv, g_dinv);
    cudaGetSymbolAddress((void**)&Ahi,  g_Ahi);
    cudaGetSymbolAddress((void**)&Alo,  g_Alo);
    cudaGetSymbolAddress((void**)&Bhi,  g_Bhi);
    cudaGetSymbolAddress((void**)&Blo,  g_Blo);
    cudaGetSymbolAddress((void**)&cnt,     g_cnt);
    cudaGetSymbolAddress((void**)&rowptr,  g_rowptr);
    cudaGetSymbolAddress((void**)&cursor,  g_cursor);
    cudaGetSymbolAddress((void**)&blksum,  g_blksum);
    cudaGetSymbolAddress((void**)&csr,     g_csr);

    cudaFuncSetAttribute(k_gemm_mma, cudaFuncAttributeMaxDynamicSharedMemorySize, SM_GEMM);

    // degree + counts
    k_deg_init <<<(N_NODES + 255) / 256, 256>>>(deg, cnt);
    k_deg_count<<<(E_EDGES + 255) / 256, 256>>>(ei, ew, deg, cnt);

    // CSR build (k_scan_final also computes dinv)
    k_scan_block<<<NB_SCAN, 256>>>(cnt, rowptr, blksum);
    k_scan_tops <<<1, 256>>>(blksum);
    k_scan_final<<<(N_NODES + 255) / 256, 256>>>(rowptr, blksum, cursor, deg, dinv);
    k_fill      <<<(E_EDGES + 255) / 256, 256>>>(ei, ew, dinv, cursor, csr);

    // split + transpose all 5 weight matrices in one kernel
    k_split_B<<<(5 * D * D + 255) / 256, 256>>>(conv_w, post_w, Bhi, Blo);

    // LN for layer 0 reads emb directly (no h=emb copy needed)
    k_ln_split<<<(N_NODES * 32 + 255) / 256, 256>>>(emb, ln_w, ln_b, Ahi, Alo);

    int gemm_grid = N_PAD / BM;   // 391 CTAs, one per 128-row band

    for (int i = 0; i < L; i++) {
        k_gemm_mma<<<gemm_grid, 256, SM_GEMM>>>(Ahi, Alo,
                                                Bhi + (size_t)i * D * D,
                                                Blo + (size_t)i * D * D,
                                                nullptr, zw, zwh, N_PAD);
        const float* nlw = ln_w + (size_t)(i + 1) * D;
        const float* nlb = ln_b + (size_t)(i + 1) * D;
        int do_ln = (i < L - 1) ? 1 : 0;
        if (!do_ln) { nlw = ln_w; nlb = ln_b; }
        const float* h_in = (i == 0) ? emb : h;
        k_agg_fused<<<(N_NODES * 32 + 255) / 256, 256>>>(rowptr, csr,
                                                         zw, zwh,
                                                         conv_b + (size_t)i * D,
                                                         dinv, h_in, h, nlw, nlb,
                                                         Ahi, Alo, do_ln);
    }

    // final projection (no fp16 mirror needed)
    k_gemm_mma<<<gemm_grid, 256, SM_GEMM>>>(Ahi, Alo,
                                            Bhi + (size_t)4 * D * D,
                                            Blo + (size_t)4 * D * D,
                                            post_b, out, nullptr, N_NODES);
}

// round 16
// speedup vs baseline: 1.5144x; 1.0473x over previous
#include <cuda_runtime.h>
#include <cuda_bf16.h>
#include <cuda_fp16.h>
#include <math.h>
#include <stdint.h>

#define N_NODES 50000
#define N_PAD   50048          // multiple of 128 for GEMM tiles
#define E_EDGES 800000
#define D       256
#define L       4
#define NB_SCAN 196            // ceil(N_NODES/256)

// ---------------- scratch (device globals; .bss zero-init, pads stay 0) ----
__device__ float g_h  [(size_t)N_PAD * D];
__device__ __half g_zwh[(size_t)N_PAD * D];   // fp16 layer activations (gather + self)
__device__ float g_deg [N_NODES];
__device__ float g_dinv[N_NODES];
__device__ __nv_bfloat16 g_Ahi[(size_t)N_PAD * D];
__device__ __nv_bfloat16 g_Alo[(size_t)N_PAD * D];
__device__ __nv_bfloat16 g_Bhi[5 * D * D];   // 4 conv layers + post_w, [n][k] K-major
__device__ __nv_bfloat16 g_Blo[5 * D * D];
// CSR (by destination): packed {src, coef_bits}
__device__ int   g_cnt    [N_NODES];
__device__ int   g_rowptr [N_NODES + 1];
__device__ int   g_cursor [N_NODES];
__device__ int   g_blksum [NB_SCAN];
__device__ int2  g_csr    [E_EDGES];

// ---------------- small helpers ----------------
__device__ __forceinline__ float gelu_exact(float x) {
    return 0.5f * x * (1.0f + erff(x * 0.70710678118654752440f));
}
__device__ __forceinline__ void mma_bf16(float* c, const uint32_t* a, const uint32_t* b) {
    asm volatile("mma.sync.aligned.m16n8k16.row.col.f32.bf16.bf16.f32 "
                 "{%0,%1,%2,%3}, {%4,%5,%6,%7}, {%8,%9}, {%0,%1,%2,%3};"
                 : "+f"(c[0]), "+f"(c[1]), "+f"(c[2]), "+f"(c[3])
                 : "r"(a[0]), "r"(a[1]), "r"(a[2]), "r"(a[3]),
                   "r"(b[0]), "r"(b[1]));
}
__device__ __forceinline__ uint32_t smem_u32(const void* p) {
    uint32_t a;
    asm("{ .reg .u64 t; cvta.to.shared.u64 t, %1; cvt.u32.u64 %0, t; }" : "=r"(a) : "l"(p));
    return a;
}
#define LDSM_X4(r0, r1, r2, r3, addr) \
    asm volatile("ldmatrix.sync.aligned.m8n8.x4.shared.b16 {%0,%1,%2,%3}, [%4];" \
                 : "=r"(r0), "=r"(r1), "=r"(r2), "=r"(r3) : "r"(addr))

// Convert packed fp16 pair (as uint32) to float2 WITHOUT any address-of.
__device__ __forceinline__ float2 h2_to_f2(uint32_t w) {
    __half2_raw r;
    r.x = (unsigned short)(w & 0xffffu);
    r.y = (unsigned short)(w >> 16);
    return __half22float2((__half2)r);
}
__device__ __forceinline__ void acc_h8(float* acc, uint4 q, float c) {
    float2 u;
    u = h2_to_f2(q.x); acc[0] = fmaf(c, u.x, acc[0]); acc[1] = fmaf(c, u.y, acc[1]);
    u = h2_to_f2(q.y); acc[2] = fmaf(c, u.x, acc[2]); acc[3] = fmaf(c, u.y, acc[3]);
    u = h2_to_f2(q.z); acc[4] = fmaf(c, u.x, acc[4]); acc[5] = fmaf(c, u.y, acc[5]);
    u = h2_to_f2(q.w); acc[6] = fmaf(c, u.x, acc[6]); acc[7] = fmaf(c, u.y, acc[7]);
}

// ---------------- degree + count ----------------
__global__ void k_deg_init(float* __restrict__ deg, int* __restrict__ cnt) {
    int i = blockIdx.x * blockDim.x + threadIdx.x;
    if (i < N_NODES) { deg[i] = 1.0f; cnt[i] = 0; }
}
__global__ void k_deg_count(const int* __restrict__ ei, const float* __restrict__ ew,
                            float* __restrict__ deg, int* __restrict__ cnt) {
    int e = blockIdx.x * blockDim.x + threadIdx.x;
    if (e < E_EDGES) {
        int dst = ei[E_EDGES + e];
        atomicAdd(&deg[dst], ew[e]);
        atomicAdd(&cnt[dst], 1);
    }
}

// ---------------- CSR: 2-level exclusive scan ----------------
__global__ void k_scan_block(const int* __restrict__ cnt, int* __restrict__ row_ptr,
                             int* __restrict__ blk_sum) {
    __shared__ int wsum[8];
    int i = blockIdx.x * 256 + threadIdx.x;
    int lane = threadIdx.x & 31, wid = threadIdx.x >> 5;
    int v = (i < N_NODES) ? cnt[i] : 0;
    int x = v;
    #pragma unroll
    for (int o = 1; o < 32; o <<= 1) {
        int y = __shfl_up_sync(0xffffffffu, x, o);
        if (lane >= o) x += y;
    }
    if (lane == 31) wsum[wid] = x;
    __syncthreads();
    if (wid == 0) {
        int s = (lane < 8) ? wsum[lane] : 0;
        #pragma unroll
        for (int o = 1; o < 8; o <<= 1) {
            int y = __shfl_up_sync(0xffffffffu, s, o);
            if (lane >= o) s += y;
        }
        if (lane < 8) wsum[lane] = s;   // inclusive warp totals
    }
    __syncthreads();
    int base = (wid > 0) ? wsum[wid - 1] : 0;
    if (i < N_NODES) row_ptr[i] = base + x - v;     // block-local exclusive
    if (threadIdx.x == 255) blk_sum[blockIdx.x] = base + x;  // block total
}
__global__ void k_scan_tops(int* __restrict__ blk_sum) {
    __shared__ int wsum[8];
    int tid = threadIdx.x;
    int lane = tid & 31, wid = tid >> 5;
    int v = (tid < NB_SCAN) ? blk_sum[tid] : 0;
    int x = v;
    #pragma unroll
    for (int o = 1; o < 32; o <<= 1) {
        int y = __shfl_up_sync(0xffffffffu, x, o);
        if (lane >= o) x += y;
    }
    if (lane == 31) wsum[wid] = x;
    __syncthreads();
    if (wid == 0) {
        int s = (lane < 8) ? wsum[lane] : 0;
        #pragma unroll
        for (int o = 1; o < 8; o <<= 1) {
            int y = __shfl_up_sync(0xffffffffu, s, o);
            if (lane >= o) s += y;
        }
        if (lane < 8) wsum[lane] = s;
    }
    __syncthreads();
    int base = (wid > 0) ? wsum[wid - 1] : 0;
    if (tid < NB_SCAN) blk_sum[tid] = base + x - v;  // exclusive block offsets
}
// finalize row_ptr, cursor AND dinv (deg is ready by this point)
__global__ void k_scan_final(int* __restrict__ row_ptr, const int* __restrict__ blk_sum,
                             int* __restrict__ cursor, const float* __restrict__ deg,
                             float* __restrict__ dinv) {
    int i = blockIdx.x * blockDim.x + threadIdx.x;
    if (i < N_NODES) {
        int r = row_ptr[i] + blk_sum[i >> 8];
        row_ptr[i] = r;
        cursor[i] = r;
        dinv[i] = rsqrtf(fmaxf(deg[i], 1e-12f));
    }
    if (i == 0) row_ptr[N_NODES] = E_EDGES;
}
__global__ void k_fill(const int* __restrict__ ei, const float* __restrict__ ew,
                       const float* __restrict__ dinv, int* __restrict__ cursor,
                       int2* __restrict__ csr) {
    int e = blockIdx.x * blockDim.x + threadIdx.x;
    if (e >= E_EDGES) return;
    int src = ei[e];
    int dst = ei[E_EDGES + e];
    int pos = atomicAdd(&cursor[dst], 1);
    float coef = dinv[src] * ew[e] * dinv[dst];
    csr[pos] = make_int2(src, __float_as_int(coef));
}

// ---------------- LayerNorm fused with bf16 hi/lo split: one warp per node ----
__global__ void k_ln_split(const float* __restrict__ h, const float* __restrict__ w,
                           const float* __restrict__ b,
                           __nv_bfloat16* __restrict__ Ahi,
                           __nv_bfloat16* __restrict__ Alo) {
    int gtid = blockIdx.x * blockDim.x + threadIdx.x;
    int node = gtid >> 5;
    int lane = threadIdx.x & 31;
    if (node >= N_NODES) return;

    const float4* hp = (const float4*)(h + (size_t)node * D);
    float4 v0 = hp[lane * 2 + 0];
    float4 v1 = hp[lane * 2 + 1];

    float s = v0.x + v0.y + v0.z + v0.w + v1.x + v1.y + v1.z + v1.w;
    #pragma unroll
    for (int o = 16; o; o >>= 1) s += __shfl_xor_sync(0xffffffffu, s, o);
    float mu = s * (1.0f / 256.0f);

    float dd[8] = {v0.x - mu, v0.y - mu, v0.z - mu, v0.w - mu,
                   v1.x - mu, v1.y - mu, v1.z - mu, v1.w - mu};
    float q = 0.f;
    #pragma unroll
    for (int j = 0; j < 8; j++) q += dd[j] * dd[j];
    #pragma unroll
    for (int o = 16; o; o >>= 1) q += __shfl_xor_sync(0xffffffffu, q, o);
    float rs = rsqrtf(q * (1.0f / 256.0f) + 1e-5f);

    const float4* wp = (const float4*)w;
    const float4* bp = (const float4*)b;
    float4 w0 = wp[lane * 2 + 0], w1 = wp[lane * 2 + 1];
    float4 b0 = bp[lane * 2 + 0], b1 = bp[lane * 2 + 1];
    float ww[8] = {w0.x, w0.y, w0.z, w0.w, w1.x, w1.y, w1.z, w1.w};
    float bb[8] = {b0.x, b0.y, b0.z, b0.w, b1.x, b1.y, b1.z, b1.w};

    __align__(16) __nv_bfloat16 hi[8];
    __align__(16) __nv_bfloat16 lo[8];
    #pragma unroll
    for (int j = 0; j < 8; j++) {
        float o = fmaf(dd[j] * rs, ww[j], bb[j]);
        hi[j] = __float2bfloat16(o);
        lo[j] = __float2bfloat16(o - __bfloat162float(hi[j]));
    }
    *(uint4*)&Ahi[(size_t)node * D + lane * 8] = *(uint4*)hi;
    *(uint4*)&Alo[(size_t)node * D + lane * 8] = *(uint4*)lo;
}

// ---------------- weight transpose + split for all 5 matrices ----------------
__global__ void k_split_B(const float* __restrict__ conv_w, const float* __restrict__ post_w,
                          __nv_bfloat16* __restrict__ bhi,
                          __nv_bfloat16* __restrict__ blo) {
    int idx = blockIdx.x * blockDim.x + threadIdx.x;
    if (idx >= 5 * D * D) return;
    int m = idx / (D * D);
    int rem = idx - m * D * D;
    int n = rem >> 8;
    int k = rem & 255;
    const float* w = (m < 4) ? (conv_w + (size_t)m * D * D) : post_w;
    float v = w[(size_t)k * D + n];
    __nv_bfloat16 hi = __float2bfloat16(v);
    bhi[idx] = hi;
    blo[idx] = __float2bfloat16(v - __bfloat162float(hi));
}

// ---------------- HMMA GEMM: C[M,256] = A[M,256]*B^T + bias, bf16x3 split ----
// One CTA per 128-row band. A (hi+lo, full K=256) staged ONCE in smem;
// four 64-column passes restage only B. 8 warps (4m x 2n), warp tile 32x32.
// Fragment loads via ldmatrix.x4. Writes fp32 C and/or fp16 Ch (either optional).
#define BM 128
#define BNP 64                // columns per pass
#define NPASS (D / BNP)       // 4
#define ASTR 264              // row stride in bf16 (528B = 132 words; 132%32=4)

#define SA_HI 0
#define SA_LO (BM * ASTR * 2)                        // 67584
#define SB_HI (2 * BM * ASTR * 2)                    // 135168
#define SB_LO (2 * BM * ASTR * 2 + BNP * ASTR * 2)   // 168960
#define SM_GEMM (2 * BM * ASTR * 2 + 2 * BNP * ASTR * 2)   // 202752

__global__ void __launch_bounds__(256, 1)
k_gemm_mma(const __nv_bfloat16* __restrict__ Ahi, const __nv_bfloat16* __restrict__ Alo,
           const __nv_bfloat16* __restrict__ Bhi, const __nv_bfloat16* __restrict__ Blo,
           const float* __restrict__ bias, float* __restrict__ C,
           __half* __restrict__ Ch, int Mstore) {
    extern __shared__ char smem[];
    __nv_bfloat16* sAhi = (__nv_bfloat16*)(smem + SA_HI);
    __nv_bfloat16* sAlo = (__nv_bfloat16*)(smem + SA_LO);
    __nv_bfloat16* sBhi = (__nv_bfloat16*)(smem + SB_HI);
    __nv_bfloat16* sBlo = (__nv_bfloat16*)(smem + SB_LO);

    int tid = threadIdx.x;
    int lane = tid & 31;
    int wid = tid >> 5;          // 0..7
    int wrow = wid & 3;          // 0..3 -> 32-row band
    int wcol = wid >> 2;         // 0..1 -> 32-col band (within 64-col pass)
    int row0 = blockIdx.x * BM;

    int lr = lane >> 2;
    int lc = (lane & 3) * 2;

    // ldmatrix per-lane addressing
    int g  = lane >> 3;
    int rg = lane & 7;
    uint32_t offA[2];
    #pragma unroll
    for (int mt = 0; mt < 2; mt++)
        offA[mt] = (uint32_t)(((wrow * 32 + mt * 16 + (g & 1) * 8 + rg) * ASTR
                               + (g >> 1) * 8) * 2);
    uint32_t offB[2];
    #pragma unroll
    for (int ntp = 0; ntp < 2; ntp++)
        offB[ntp] = (uint32_t)(((wcol * 32 + ntp * 16 + (g >> 1) * 8 + rg) * ASTR
                                + (g & 1) * 8) * 2);

    uint32_t aU32[2] = { smem_u32(sAhi), smem_u32(sAlo) };
    uint32_t bU32[2] = { smem_u32(sBhi), smem_u32(sBlo) };

    // ---- stage A (hi+lo), full K=256 ----
    #pragma unroll
    for (int i = 0; i < 16; i++) {
        int idx = tid + i * 256;
        int r = idx >> 5;
        int c = (idx & 31) * 8;
        size_t gg = (size_t)(row0 + r) * D + c;
        *(uint4*)&sAhi[r * ASTR + c] = *(const uint4*)&Ahi[gg];
        *(uint4*)&sAlo[r * ASTR + c] = *(const uint4*)&Alo[gg];
    }

    #pragma unroll
    for (int pass = 0; pass < NPASS; pass++) {
        int col0 = pass * BNP;
        __syncthreads();
        #pragma unroll
        for (int i = 0; i < 8; i++) {
            int idx = tid + i * 256;
            int r = idx >> 5;
            int c = (idx & 31) * 8;
            size_t gg = (size_t)(col0 + r) * D + c;
            *(uint4*)&sBhi[r * ASTR + c] = *(const uint4*)&Bhi[gg];
            *(uint4*)&sBlo[r * ASTR + c] = *(const uint4*)&Blo[gg];
        }
        __syncthreads();

        float acc[2][4][4];
        #pragma unroll
        for (int mt = 0; mt < 2; mt++)
            #pragma unroll
            for (int nt = 0; nt < 4; nt++)
                #pragma unroll
                for (int j = 0; j < 4; j++) acc[mt][nt][j] = 0.0f;

        #pragma unroll
        for (int p = 0; p < 3; p++) {
            uint32_t aB = aU32[(p == 2) ? 1 : 0];
            uint32_t bB = bU32[(p == 1) ? 1 : 0];
            #pragma unroll
            for (int ks = 0; ks < 16; ks++) {
                uint32_t ka = (uint32_t)(ks * 16 * 2);
                uint32_t afr[2][4];
                LDSM_X4(afr[0][0], afr[0][1], afr[0][2], afr[0][3], aB + offA[0] + ka);
                LDSM_X4(afr[1][0], afr[1][1], afr[1][2], afr[1][3], aB + offA[1] + ka);
                uint32_t bfr[4][2];
                LDSM_X4(bfr[0][0], bfr[0][1], bfr[1][0], bfr[1][1], bB + offB[0] + ka);
                LDSM_X4(bfr[2][0], bfr[2][1], bfr[3][0], bfr[3][1], bB + offB[1] + ka);
                #pragma unroll
                for (int mt = 0; mt < 2; mt++)
                    #pragma unroll
                    for (int nt = 0; nt < 4; nt++)
                        mma_bf16(acc[mt][nt], afr[mt], bfr[nt]);
            }
        }

        // ---- epilogue for this pass ----
        #pragma unroll
        for (int mt = 0; mt < 2; mt++) {
            int r0 = row0 + wrow * 32 + mt * 16 + lr;
            #pragma unroll
            for (int nt = 0; nt < 4; nt++) {
                int cc = col0 + wcol * 32 + nt * 8 + lc;
                float bx = 0.f, by = 0.f;
                if (bias) { bx = bias[cc]; by = bias[cc + 1]; }
                if (r0 < Mstore) {
                    float2 o = make_float2(acc[mt][nt][0] + bx, acc[mt][nt][1] + by);
                    if (C)  *(float2*)&C[(size_t)r0 * D + cc] = o;
                    if (Ch) *(__half2*)&Ch[(size_t)r0 * D + cc] = __floats2half2_rn(o.x, o.y);
                }
                if (r0 + 8 < Mstore) {
                    float2 o = make_float2(acc[mt][nt][2] + bx, acc[mt][nt][3] + by);
                    if (C)  *(float2*)&C[(size_t)(r0 + 8) * D + cc] = o;
                    if (Ch) *(__half2*)&Ch[(size_t)(r0 + 8) * D + cc] = __floats2half2_rn(o.x, o.y);
                }
            }
        }
    }
}

// ---------------- fused aggregate + GELU + residual + next-layer LN/split ----
// h_out[dst] = h_in[dst] + gelu( conv_b + dinv^2*zwh[dst] + sum coef*zwh[src] )
__global__ void __launch_bounds__(256)
k_agg_fused(const int* __restrict__ row_ptr, const int2* __restrict__ csr,
            const __half* __restrict__ zwh,
            const float* __restrict__ bias, const float* __restrict__ dinv,
            const float* __restrict__ h_in, float* __restrict__ h_out,
            const float* __restrict__ lnw, const float* __restrict__ lnb,
            __nv_bfloat16* __restrict__ Ahi, __nv_bfloat16* __restrict__ Alo,
            int do_ln) {
    int gtid = blockIdx.x * blockDim.x + threadIdx.x;
    int node = gtid >> 5;
    int lane = threadIdx.x & 31;
    if (node >= N_NODES) return;

    int beg = row_ptr[node];
    int end = row_ptr[node + 1];
    float s = dinv[node];
    s = s * s;

    const float4* bp = (const float4*)bias + lane * 2;
    float4 b0 = bp[0], b1 = bp[1];
    float acc[8] = {b0.x, b0.y, b0.z, b0.w, b1.x, b1.y, b1.z, b1.w};

    // self-loop term from fp16 activations
    {
        uint4 qs = *((const uint4*)(zwh + (size_t)node * D) + lane);
        acc_h8(acc, qs, s);
    }

    int e = beg;
    for (; e + 8 <= end; e += 8) {
        int2 e1 = csr[e],     e2 = csr[e + 1], e3 = csr[e + 2], e4 = csr[e + 3];
        int2 e5 = csr[e + 4], e6 = csr[e + 5], e7 = csr[e + 6], e8 = csr[e + 7];
        uint4 q1 = *((const uint4*)(zwh + (size_t)e1.x * D) + lane);
        uint4 q2 = *((const uint4*)(zwh + (size_t)e2.x * D) + lane);
        uint4 q3 = *((const uint4*)(zwh + (size_t)e3.x * D) + lane);
        uint4 q4 = *((const uint4*)(zwh + (size_t)e4.x * D) + lane);
        uint4 q5 = *((const uint4*)(zwh + (size_t)e5.x * D) + lane);
        uint4 q6 = *((const uint4*)(zwh + (size_t)e6.x * D) + lane);
        uint4 q7 = *((const uint4*)(zwh + (size_t)e7.x * D) + lane);
        uint4 q8 = *((const uint4*)(zwh + (size_t)e8.x * D) + lane);
        acc_h8(acc, q1, __int_as_float(e1.y));
        acc_h8(acc, q2, __int_as_float(e2.y));
        acc_h8(acc, q3, __int_as_float(e3.y));
        acc_h8(acc, q4, __int_as_float(e4.y));
        acc_h8(acc, q5, __int_as_float(e5.y));
        acc_h8(acc, q6, __int_as_float(e6.y));
        acc_h8(acc, q7, __int_as_float(e7.y));
        acc_h8(acc, q8, __int_as_float(e8.y));
    }
    for (; e + 2 <= end; e += 2) {
        int2 e1 = csr[e], e2 = csr[e + 1];
        uint4 q1 = *((const uint4*)(zwh + (size_t)e1.x * D) + lane);
        uint4 q2 = *((const uint4*)(zwh + (size_t)e2.x * D) + lane);
        acc_h8(acc, q1, __int_as_float(e1.y));
        acc_h8(acc, q2, __int_as_float(e2.y));
    }
    if (e < end) {
        int2 e1 = csr[e];
        uint4 q1 = *((const uint4*)(zwh + (size_t)e1.x * D) + lane);
        acc_h8(acc, q1, __int_as_float(e1.y));
    }

    // residual (read h_in, write h_out)
    const float4* hip = (const float4*)(h_in + (size_t)node * D) + lane * 2;
    float4 h0 = hip[0], h1 = hip[1];
    float hv[8];
    hv[0] = h0.x + gelu_exact(acc[0]); hv[1] = h0.y + gelu_exact(acc[1]);
    hv[2] = h0.z + gelu_exact(acc[2]); hv[3] = h0.w + gelu_exact(acc[3]);
    hv[4] = h1.x + gelu_exact(acc[4]); hv[5] = h1.y + gelu_exact(acc[5]);
    hv[6] = h1.z + gelu_exact(acc[6]); hv[7] = h1.w + gelu_exact(acc[7]);
    float4* hop = (float4*)(h_out + (size_t)node * D) + lane * 2;
    hop[0] = make_float4(hv[0], hv[1], hv[2], hv[3]);
    hop[1] = make_float4(hv[4], hv[5], hv[6], hv[7]);

    // next-layer LN (or identity) + bf16 hi/lo split
    float ov[8];
    if (do_ln) {
        float sum = hv[0] + hv[1] + hv[2] + hv[3] + hv[4] + hv[5] + hv[6] + hv[7];
        #pragma unroll
        for (int o = 16; o; o >>= 1) sum += __shfl_xor_sync(0xffffffffu, sum, o);
        float mu = sum * (1.0f / 256.0f);
        float q = 0.f;
        #pragma unroll
        for (int j = 0; j < 8; j++) { float d = hv[j] - mu; q += d * d; }
        #pragma unroll
        for (int o = 16; o; o >>= 1) q += __shfl_xor_sync(0xffffffffu, q, o);
        float rsg = rsqrtf(q * (1.0f / 256.0f) + 1e-5f);

        const float4* wp = (const float4*)lnw + lane * 2;
        const float4* lbp = (const float4*)lnb + lane * 2;
        float4 w0 = wp[0], w1 = wp[1];
        float4 lb0 = lbp[0], lb1 = lbp[1];
        float ww[8] = {w0.x, w0.y, w0.z, w0.w, w1.x, w1.y, w1.z, w1.w};
        float bb2[8] = {lb0.x, lb0.y, lb0.z, lb0.w, lb1.x, lb1.y, lb1.z, lb1.w};
        #pragma unroll
        for (int j = 0; j < 8; j++)
            ov[j] = fmaf((hv[j] - mu) * rsg, ww[j], bb2[j]);
    } else {
        #pragma unroll
        for (int j = 0; j < 8; j++) ov[j] = hv[j];
    }

    __align__(16) __nv_bfloat16 hi[8];
    __align__(16) __nv_bfloat16 lo[8];
    #pragma unroll
    for (int j = 0; j < 8; j++) {
        hi[j] = __float2bfloat16(ov[j]);
        lo[j] = __float2bfloat16(ov[j] - __bfloat162float(hi[j]));
    }
    *(uint4*)&Ahi[(size_t)node * D + lane * 8] = *(uint4*)hi;
    *(uint4*)&Alo[(size_t)node * D + lane * 8] = *(uint4*)lo;
}

// ---------------- launch ----------------
extern "C" void kernel_launch(void* const* d_in, const int* in_sizes, int n_in,
                              void* d_out, int out_size) {
    const int*   ei     = (const int*)  d_in[1];
    const float* ew     = (const float*)d_in[2];
    const float* emb    = (const float*)d_in[3];
    const float* ln_w   = (const float*)d_in[4];
    const float* ln_b   = (const float*)d_in[5];
    const float* conv_w = (const float*)d_in[6];
    const float* conv_b = (const float*)d_in[7];
    const float* post_w = (const float*)d_in[8];
    const float* post_b = (const float*)d_in[9];
    float* out = (float*)d_out;

    float *h, *deg, *dinv;
    __half *zwh;
    int *cnt, *rowptr, *cursor, *blksum;
    int2 *csr;
    __nv_bfloat16 *Ahi, *Alo, *Bhi, *Blo;
    cudaGetSymbolAddress((void**)&h,    g_h);
    cudaGetSymbolAddress((void**)&zwh,  g_zwh);
    cudaGetSymbolAddress((void**)&deg,  g_deg);
    cudaGetSymbolAddress((void**)&dinv, g_dinv);
    cudaGetSymbolAddress((void**)&Ahi,  g_Ahi);
    cudaGetSymbolAddress((void**)&Alo,  g_Alo);
    cudaGetSymbolAddress((void**)&Bhi,  g_Bhi);
    cudaGetSymbolAddress((void**)&Blo,  g_Blo);
    cudaGetSymbolAddress((void**)&cnt,     g_cnt);
    cudaGetSymbolAddress((void**)&rowptr,  g_rowptr);
    cudaGetSymbolAddress((void**)&cursor,  g_cursor);
    cudaGetSymbolAddress((void**)&blksum,  g_blksum);
    cudaGetSymbolAddress((void**)&csr,     g_csr);

    cudaFuncSetAttribute(k_gemm_mma, cudaFuncAttributeMaxDynamicSharedMemorySize, SM_GEMM);

    // degree + counts
    k_deg_init <<<(N_NODES + 255) / 256, 256>>>(deg, cnt);
    k_deg_count<<<(E_EDGES + 255) / 256, 256>>>(ei, ew, deg, cnt);

    // CSR build (k_scan_final also computes dinv)
    k_scan_block<<<NB_SCAN, 256>>>(cnt, rowptr, blksum);
    k_scan_tops <<<1, 256>>>(blksum);
    k_scan_final<<<(N_NODES + 255) / 256, 256>>>(rowptr, blksum, cursor, deg, dinv);
    k_fill      <<<(E_EDGES + 255) / 256, 256>>>(ei, ew, dinv, cursor, csr);

    // split + transpose all 5 weight matrices in one kernel
    k_split_B<<<(5 * D * D + 255) / 256, 256>>>(conv_w, post_w, Bhi, Blo);

    // LN for layer 0 reads emb directly (no h=emb copy needed)
    k_ln_split<<<(N_NODES * 32 + 255) / 256, 256>>>(emb, ln_w, ln_b, Ahi, Alo);

    int gemm_grid = N_PAD / BM;   // 391 CTAs, one per 128-row band

    for (int i = 0; i < L; i++) {
        // conv layers need only the fp16 activations
        k_gemm_mma<<<gemm_grid, 256, SM_GEMM>>>(Ahi, Alo,
                                                Bhi + (size_t)i * D * D,
                                                Blo + (size_t)i * D * D,
                                                nullptr, nullptr, zwh, N_PAD);
        const float* nlw = ln_w + (size_t)(i + 1) * D;
        const float* nlb = ln_b + (size_t)(i + 1) * D;
        int do_ln = (i < L - 1) ? 1 : 0;
        if (!do_ln) { nlw = ln_w; nlb = ln_b; }
        const float* h_in = (i == 0) ? emb : h;
        k_agg_fused<<<(N_NODES * 32 + 255) / 256, 256>>>(rowptr, csr, zwh,
                                                         conv_b + (size_t)i * D,
                                                         dinv, h_in, h, nlw, nlb,
                                                         Ahi, Alo, do_ln);
    }

    // final projection: fp32 output only
    k_gemm_mma<<<gemm_grid, 256, SM_GEMM>>>(Ahi, Alo,
                                            Bhi + (size_t)4 * D * D,
                                            Blo + (size_t)4 * D * D,
                                            post_b, out, nullptr, N_NODES);
}